// round 15
// baseline (speedup 1.0000x reference)
#include <cuda_runtime.h>
#include <cuda_fp16.h>
#include <cstdint>
#include <math.h>

// Shapes (fixed)
#define BB 8
#define SS 2048
#define QQ 2048
#define DD 1024

// ---------------------------------------------------------------------------
// Scratch (device globals). fp16 operands, f32 where accumulation precision matters.
// ---------------------------------------------------------------------------
__device__ __half g_t1h[(size_t)BB * SS * QQ];        // tanh(f_att) fp16
__device__ float  g_t2[(size_t)BB * SS * QQ];         // sim (f32 for softmax)
__device__ __half g_ph[(size_t)BB * SS * QQ];         // softmax probs fp16
__device__ __half g_wkTh[(size_t)QQ * DD];            // wkT[q][d]
__device__ __half g_kernTh[(size_t)QQ * QQ];          // kernT[t][q]
__device__ __half g_srch[(size_t)BB * SS * DD];       // src fp16
__device__ __half g_qryh[(size_t)BB * QQ * DD];       // query fp16
__device__ __half g_wqh[(size_t)SS * DD];             // wq fp16

// ---------------------------------------------------------------------------
// PTX helpers (baseline PTX)
// ---------------------------------------------------------------------------
__device__ __forceinline__ uint32_t h2_as_u32(__half2 h) {
    uint32_t u;
    __builtin_memcpy(&u, &h, sizeof(u));
    return u;
}

__device__ __forceinline__ void mma_f16(float* d, const uint32_t* a, const uint32_t* b) {
    asm volatile(
        "mma.sync.aligned.m16n8k16.row.col.f32.f16.f16.f32 "
        "{%0,%1,%2,%3}, {%4,%5,%6,%7}, {%8,%9}, {%0,%1,%2,%3};\n"
        : "+f"(d[0]), "+f"(d[1]), "+f"(d[2]), "+f"(d[3])
        : "r"(a[0]), "r"(a[1]), "r"(a[2]), "r"(a[3]), "r"(b[0]), "r"(b[1]));
}

__device__ __forceinline__ void ldsm_x4(uint32_t* r, uint32_t saddr) {
    asm volatile("ldmatrix.sync.aligned.m8n8.x4.shared.b16 {%0,%1,%2,%3}, [%4];"
                 : "=r"(r[0]), "=r"(r[1]), "=r"(r[2]), "=r"(r[3])
                 : "r"(saddr));
}
__device__ __forceinline__ void ldsm_x4_t(uint32_t* r, uint32_t saddr) {
    asm volatile("ldmatrix.sync.aligned.m8n8.x4.trans.shared.b16 {%0,%1,%2,%3}, [%4];"
                 : "=r"(r[0]), "=r"(r[1]), "=r"(r[2]), "=r"(r[3])
                 : "r"(saddr));
}

__device__ __forceinline__ void cp_async16(uint32_t smem_addr, const void* gptr) {
    asm volatile("cp.async.cg.shared.global [%0], [%1], 16;"
                 :: "r"(smem_addr), "l"(gptr));
}
#define CP_COMMIT() asm volatile("cp.async.commit_group;" ::: "memory")
#define CP_WAIT1()  asm volatile("cp.async.wait_group 1;" ::: "memory")

// ---------------------------------------------------------------------------
// Geometry (round-14 proven): 128x128 CTA tile, BK=64 halves, 256 threads,
// 8 warps = 4(M) x 2(N), warp tile 32x64. 3-stage cp.async, wait_group 1.
// ---------------------------------------------------------------------------
#define BM 128
#define BN 128
#define BK 64
#define LDTH 72                             // MK row stride (halves): 144B, LDSM conflict-free
#define LDMH 136                            // KM row stride (halves): 272B, conflict-free
#define STG_MK (BM * LDTH * 2)              // 18432 B / operand / stage
#define GSMEM_MK (6 * STG_MK)               // 110592 B (3 stages x 2 operands)
#define STG_KM (BK * LDMH * 2)              // 17408 B
#define GSMEM_KM (6 * STG_KM)               // 104448 B

// rotating 3-stage offset (no modulo)
#define ROT3(off, stg) do { (off) += (stg); if ((off) == 3u * (stg)) (off) = 0u; } while (0)

// per-thread LDSM source byte offsets within one MK stage (32x64 warp tile)
struct LdsmOffs { uint32_t a[2]; uint32_t b[4]; };

__device__ __forceinline__ LdsmOffs make_offs_mk(int warp_row, int warp_col, int lane) {
    LdsmOffs o;
    const int sel = lane >> 3, rin = lane & 7;
#pragma unroll
    for (int i = 0; i < 2; i++) {
        int r = warp_row * 32 + i * 16 + (sel & 1) * 8 + rin;   // m row
        int c = (sel >> 1) * 8;                                 // k halves
        o.a[i] = (uint32_t)((r * LDTH + c) * 2);
    }
#pragma unroll
    for (int jp = 0; jp < 4; jp++) {
        int n = warp_col * 64 + jp * 16 + (sel >> 1) * 8 + rin; // n row
        int c = (sel & 1) * 8;
        o.b[jp] = (uint32_t)((n * LDTH + c) * 2);
    }
    return o;
}

// one k16 step (MK): 6 LDSM.x4 + 16 MMA
__device__ __forceinline__ void mma_step_mk(float acc[2][8][4],
                                            uint32_t aBase, uint32_t bBase,
                                            const LdsmOffs& o, int ks) {
    const uint32_t kadd = ks * 32;   // 16 halves = 32 B
    uint32_t afr[2][4];
    ldsm_x4(afr[0], aBase + o.a[0] + kadd);
    ldsm_x4(afr[1], aBase + o.a[1] + kadd);
    uint32_t bfr[4][4];
#pragma unroll
    for (int jp = 0; jp < 4; jp++)
        ldsm_x4(bfr[jp], bBase + o.b[jp] + kadd);
#pragma unroll
    for (int i = 0; i < 2; i++)
#pragma unroll
        for (int j = 0; j < 8; j++)
            mma_f16(acc[i][j], afr[i], &bfr[j >> 1][(j & 1) * 2]);
}

// ============================================================================
// Kernel A: merged f_att GEMM (MK). K=2048 as two 1024 halves:
//   tiles 0..15: A=srch[b], B=wkTh ; tiles 16..31: A=wqh, B=qryh[b]
// Epilogue: tanhf -> fp16 g_t1h.
// ============================================================================
__global__ void __launch_bounds__(256, 2)
gemm_fatt()
{
    extern __shared__ uint32_t smem[];
    const uint32_t sBase = (uint32_t)__cvta_generic_to_shared(smem);
    const uint32_t asBase = sBase;
    const uint32_t bsBase = sBase + 3 * STG_MK;

    const int tid = threadIdx.x;
    const int wid = tid >> 5;
    const int lane = tid & 31;
    const int warp_row = wid >> 1;
    const int warp_col = wid & 1;

    const int b  = blockIdx.z;
    const int m0 = blockIdx.y * BM;
    const int n0 = blockIdx.x * BN;

    const __half* a_half[2] = { g_srch + (size_t)b * SS * DD + (size_t)m0 * DD,
                                g_wqh  + (size_t)m0 * DD };
    const __half* b_half[2] = { g_wkTh + (size_t)n0 * DD,
                                g_qryh + (size_t)b * QQ * DD + (size_t)n0 * DD };

    const int l_row = tid >> 3;          // 0..31
    const int l_c8  = (tid & 7) * 8;     // halves 0..56

    uint32_t wOff[4];
#pragma unroll
    for (int u = 0; u < 4; u++)
        wOff[u] = (uint32_t)(((l_row + 32 * u) * LDTH + l_c8) * 2);

    const LdsmOffs offs = make_offs_mk(warp_row, warp_col, lane);

    float acc[2][8][4];
#pragma unroll
    for (int i = 0; i < 2; i++)
#pragma unroll
        for (int j = 0; j < 8; j++)
#pragma unroll
            for (int r = 0; r < 4; r++) acc[i][j][r] = 0.f;

    const int ntiles = 2048 / BK;   // 32 (16 per half)

    // prologue: tiles 0,1 (both half 0)
#pragma unroll
    for (int p = 0; p < 2; p++) {
        const int k0 = p * BK;
        const __half* ap = a_half[0] + (size_t)l_row * DD + k0 + l_c8;
        const __half* bp = b_half[0] + (size_t)l_row * DD + k0 + l_c8;
        const uint32_t so = (uint32_t)p * STG_MK;
#pragma unroll
        for (int u = 0; u < 4; u++) {
            cp_async16(asBase + so + wOff[u], ap + (size_t)(32 * u) * DD);
            cp_async16(bsBase + so + wOff[u], bp + (size_t)(32 * u) * DD);
        }
        CP_COMMIT();
    }

    uint32_t co = 0;                       // compute stage offset
    uint32_t po = 2u * STG_MK;             // prefetch stage offset
    for (int t = 0; t < ntiles; t++) {
        CP_WAIT1();
        __syncthreads();

        if (t + 2 < ntiles) {
            const int tt = t + 2;
            const int h  = tt >> 4;
            const int k0 = (tt & 15) * BK;
            const __half* ap = a_half[h] + (size_t)l_row * DD + k0 + l_c8;
            const __half* bp = b_half[h] + (size_t)l_row * DD + k0 + l_c8;
#pragma unroll
            for (int u = 0; u < 4; u++) {
                cp_async16(asBase + po + wOff[u], ap + (size_t)(32 * u) * DD);
                cp_async16(bsBase + po + wOff[u], bp + (size_t)(32 * u) * DD);
            }
            CP_COMMIT();
        }
        ROT3(po, (uint32_t)STG_MK);

#pragma unroll
        for (int ks = 0; ks < 4; ks++)
            mma_step_mk(acc, asBase + co, bsBase + co, offs, ks);
        ROT3(co, (uint32_t)STG_MK);
    }

    __half* Cb = g_t1h + (size_t)b * SS * QQ;
#pragma unroll
    for (int i = 0; i < 2; i++) {
        const int row0 = m0 + warp_row * 32 + i * 16 + (lane >> 2);
#pragma unroll
        for (int j = 0; j < 8; j++) {
            const int col = n0 + warp_col * 64 + j * 8 + 2 * (lane & 3);
#pragma unroll
            for (int r = 0; r < 2; r++) {
                const size_t off = (size_t)(row0 + r * 8) * QQ + col;
                __half2 h = __floats2half2_rn(tanhf(acc[i][j][r * 2 + 0]),
                                              tanhf(acc[i][j][r * 2 + 1]));
                *reinterpret_cast<__half2*>(Cb + off) = h;
            }
        }
    }
}

// ============================================================================
// Kernel B: sim GEMM (MK). C[b][m][n] = sum_k t1h[b][m][k] * kernTh[n][k], K=2048.
// ============================================================================
__global__ void __launch_bounds__(256, 2)
gemm_sim()
{
    extern __shared__ uint32_t smem[];
    const uint32_t sBase = (uint32_t)__cvta_generic_to_shared(smem);
    const uint32_t asBase = sBase;
    const uint32_t bsBase = sBase + 3 * STG_MK;

    const int tid = threadIdx.x;
    const int wid = tid >> 5;
    const int lane = tid & 31;
    const int warp_row = wid >> 1;
    const int warp_col = wid & 1;

    const int b  = blockIdx.z;
    const int m0 = blockIdx.y * BM;
    const int n0 = blockIdx.x * BN;

    const __half* Ab = g_t1h + (size_t)b * SS * QQ + (size_t)m0 * QQ;
    const __half* Bb = g_kernTh + (size_t)n0 * QQ;

    const int l_row = tid >> 3;
    const int l_c8  = (tid & 7) * 8;

    uint32_t wOff[4];
#pragma unroll
    for (int u = 0; u < 4; u++)
        wOff[u] = (uint32_t)(((l_row + 32 * u) * LDTH + l_c8) * 2);

    const LdsmOffs offs = make_offs_mk(warp_row, warp_col, lane);

    float acc[2][8][4];
#pragma unroll
    for (int i = 0; i < 2; i++)
#pragma unroll
        for (int j = 0; j < 8; j++)
#pragma unroll
            for (int r = 0; r < 4; r++) acc[i][j][r] = 0.f;

    const int ntiles = QQ / BK;   // 32

#pragma unroll
    for (int p = 0; p < 2; p++) {
        const int k0 = p * BK;
        const __half* ap = Ab + (size_t)l_row * QQ + k0 + l_c8;
        const __half* bp = Bb + (size_t)l_row * QQ + k0 + l_c8;
        const uint32_t so = (uint32_t)p * STG_MK;
#pragma unroll
        for (int u = 0; u < 4; u++) {
            cp_async16(asBase + so + wOff[u], ap + (size_t)(32 * u) * QQ);
            cp_async16(bsBase + so + wOff[u], bp + (size_t)(32 * u) * QQ);
        }
        CP_COMMIT();
    }

    uint32_t co = 0;
    uint32_t po = 2u * STG_MK;
    for (int t = 0; t < ntiles; t++) {
        CP_WAIT1();
        __syncthreads();

        if (t + 2 < ntiles) {
            const int k0 = (t + 2) * BK;
            const __half* ap = Ab + (size_t)l_row * QQ + k0 + l_c8;
            const __half* bp = Bb + (size_t)l_row * QQ + k0 + l_c8;
#pragma unroll
            for (int u = 0; u < 4; u++) {
                cp_async16(asBase + po + wOff[u], ap + (size_t)(32 * u) * QQ);
                cp_async16(bsBase + po + wOff[u], bp + (size_t)(32 * u) * QQ);
            }
            CP_COMMIT();
        }
        ROT3(po, (uint32_t)STG_MK);

#pragma unroll
        for (int ks = 0; ks < 4; ks++)
            mma_step_mk(acc, asBase + co, bsBase + co, offs, ks);
        ROT3(co, (uint32_t)STG_MK);
    }

    float* Cb = g_t2 + (size_t)b * SS * QQ;
#pragma unroll
    for (int i = 0; i < 2; i++) {
        const int row0 = m0 + warp_row * 32 + i * 16 + (lane >> 2);
#pragma unroll
        for (int j = 0; j < 8; j++) {
            const int col = n0 + warp_col * 64 + j * 8 + 2 * (lane & 3);
#pragma unroll
            for (int r = 0; r < 2; r++) {
                const size_t off = (size_t)(row0 + r * 8) * QQ + col;
                float2 v;
                v.x = acc[i][j][r * 2 + 0];
                v.y = acc[i][j][r * 2 + 1];
                *reinterpret_cast<float2*>(Cb + off) = v;
            }
        }
    }
}

// ============================================================================
// Kernel C: out[b][q][d] = sum_s ph[b][s][q] * srch[b][s][d]  (KM layout, K=s)
// ldmatrix.trans both operands. BK=64, 3-stage.
// ============================================================================
__global__ void __launch_bounds__(256, 2)
gemm_out(float* __restrict__ C)
{
    extern __shared__ uint32_t smem[];
    const uint32_t sBase = (uint32_t)__cvta_generic_to_shared(smem);
    const uint32_t asBase = sBase;
    const uint32_t bsBase = sBase + 3 * STG_KM;

    const int tid = threadIdx.x;
    const int wid = tid >> 5;
    const int lane = tid & 31;
    const int warp_row = wid >> 1;
    const int warp_col = wid & 1;

    const int b  = blockIdx.z;
    const int m0 = blockIdx.y * BM;   // q
    const int n0 = blockIdx.x * BN;   // d

    const __half* Ab = g_ph + (size_t)b * SS * QQ + m0;
    const __half* Bb = g_srch + (size_t)b * SS * DD + n0;

    const int lk = tid >> 3;          // 0..31
    const int lc = (tid & 7) * 8;     // halves 0..56

    uint32_t w[4];
    int wr[4], wc[4];
#pragma unroll
    for (int u = 0; u < 4; u++) {
        wr[u] = lk + 32 * (u >> 1);
        wc[u] = lc + 64 * (u & 1);
        w[u] = (uint32_t)((wr[u] * LDMH + wc[u]) * 2);
    }

    const int sel = lane >> 3, rin = lane & 7;
    uint32_t oa[2], ob[4];
#pragma unroll
    for (int i = 0; i < 2; i++)
        oa[i] = (uint32_t)((((sel >> 1) * 8 + rin) * LDMH
                           + warp_row * 32 + i * 16 + (sel & 1) * 8) * 2);
#pragma unroll
    for (int jp = 0; jp < 4; jp++)
        ob[jp] = (uint32_t)((((sel & 1) * 8 + rin) * LDMH
                           + warp_col * 64 + jp * 16 + (sel >> 1) * 8) * 2);

    float acc[2][8][4];
#pragma unroll
    for (int i = 0; i < 2; i++)
#pragma unroll
        for (int j = 0; j < 8; j++)
#pragma unroll
            for (int r = 0; r < 4; r++) acc[i][j][r] = 0.f;

    const int ntiles = SS / BK;   // 32

#pragma unroll
    for (int p = 0; p < 2; p++) {
        const int k0 = p * BK;
        const uint32_t so = (uint32_t)p * STG_KM;
#pragma unroll
        for (int u = 0; u < 4; u++) {
            cp_async16(asBase + so + w[u], Ab + (size_t)(k0 + wr[u]) * QQ + wc[u]);
            cp_async16(bsBase + so + w[u], Bb + (size_t)(k0 + wr[u]) * DD + wc[u]);
        }
        CP_COMMIT();
    }

    uint32_t co = 0;
    uint32_t po = 2u * STG_KM;
    for (int t = 0; t < ntiles; t++) {
        CP_WAIT1();
        __syncthreads();

        if (t + 2 < ntiles) {
            const int k0 = (t + 2) * BK;
#pragma unroll
            for (int u = 0; u < 4; u++) {
                cp_async16(asBase + po + w[u], Ab + (size_t)(k0 + wr[u]) * QQ + wc[u]);
                cp_async16(bsBase + po + w[u], Bb + (size_t)(k0 + wr[u]) * DD + wc[u]);
            }
            CP_COMMIT();
        }
        ROT3(po, (uint32_t)STG_KM);

        const uint32_t aB = asBase + co;
        const uint32_t bB = bsBase + co;

#pragma unroll
        for (int ks = 0; ks < 4; ks++) {
            const uint32_t kadd = (uint32_t)(ks * 16 * LDMH * 2);
            uint32_t afr[2][4];
            ldsm_x4_t(afr[0], aB + oa[0] + kadd);
            ldsm_x4_t(afr[1], aB + oa[1] + kadd);
            uint32_t bfr[4][4];
#pragma unroll
            for (int jp = 0; jp < 4; jp++)
                ldsm_x4_t(bfr[jp], bB + ob[jp] + kadd);
#pragma unroll
            for (int i = 0; i < 2; i++)
#pragma unroll
                for (int j = 0; j < 8; j++)
                    mma_f16(acc[i][j], afr[i], &bfr[j >> 1][(j & 1) * 2]);
        }
        ROT3(co, (uint32_t)STG_KM);
    }

    float* Cb = C + (size_t)b * QQ * DD;
#pragma unroll
    for (int i = 0; i < 2; i++) {
        const int row0 = m0 + warp_row * 32 + i * 16 + (lane >> 2);
#pragma unroll
        for (int j = 0; j < 8; j++) {
            const int col = n0 + warp_col * 64 + j * 8 + 2 * (lane & 3);
#pragma unroll
            for (int r = 0; r < 2; r++) {
                const size_t off = (size_t)(row0 + r * 8) * DD + col;
                float2 v;
                v.x = acc[i][j][r * 2 + 0];
                v.y = acc[i][j][r * 2 + 1];
                *reinterpret_cast<float2*>(Cb + off) = v;
            }
        }
    }
}

// ---------------------------------------------------------------------------
// Merged elementwise f32 -> fp16 over three buffers, 4 float4 per thread.
// ---------------------------------------------------------------------------
#define CVT_N0 ((BB * SS * DD) / 4)   // src
#define CVT_N1 ((BB * QQ * DD) / 4)   // qry
#define CVT_N2 ((SS * DD) / 4)        // wq
#define CVT_TOTAL (CVT_N0 + CVT_N1 + CVT_N2)

__global__ void k_cvt_all(const float4* __restrict__ src, uint2* __restrict__ srch,
                          const float4* __restrict__ qry, uint2* __restrict__ qryh,
                          const float4* __restrict__ wq,  uint2* __restrict__ wqh)
{
    int base = (blockIdx.x * blockDim.x + threadIdx.x) * 4;
#pragma unroll
    for (int k = 0; k < 4; k++) {
        int i = base + k;
        if (i >= CVT_TOTAL) return;
        const float4* in;
        uint2* out;
        int idx;
        if (i < CVT_N0)                { in = src; out = srch; idx = i; }
        else if (i < CVT_N0 + CVT_N1)  { in = qry; out = qryh; idx = i - CVT_N0; }
        else                           { in = wq;  out = wqh;  idx = i - CVT_N0 - CVT_N1; }
        float4 v = __ldcs(&in[idx]);
        uint2 o;
        o.x = h2_as_u32(__floats2half2_rn(v.x, v.y));
        o.y = h2_as_u32(__floats2half2_rn(v.z, v.w));
        out[idx] = o;
    }
}

// ---------------------------------------------------------------------------
// Merged tiled transpose f32 -> fp16 for wk (D x Q) and kern (Q x Q).
// grid.y in [0, DD/32) -> wk ; grid.y in [DD/32, DD/32 + QQ/32) -> kern
// ---------------------------------------------------------------------------
__global__ void k_transpose2(const float* __restrict__ wk, __half* __restrict__ wkT,
                             const float* __restrict__ kern, __half* __restrict__ kernT)
{
    __shared__ float tile[32][33];
    const float* in;
    __half* out;
    int R, C, r0;
    if (blockIdx.y < DD / 32) {
        in = wk; out = wkT; R = DD; C = QQ; r0 = blockIdx.y * 32;
    } else {
        in = kern; out = kernT; R = QQ; C = QQ; r0 = (blockIdx.y - DD / 32) * 32;
    }
    const int c0 = blockIdx.x * 32;

#pragma unroll
    for (int i = threadIdx.y; i < 32; i += 8)
        tile[i][threadIdx.x] = in[(size_t)(r0 + i) * C + c0 + threadIdx.x];
    __syncthreads();
#pragma unroll
    for (int i = threadIdx.y; i < 32; i += 8)
        out[(size_t)(c0 + i) * R + r0 + threadIdx.x] = __float2half_rn(tile[threadIdx.x][i]);
}

// ---------------------------------------------------------------------------
// SMEM-resident row softmax: read f32 g_t2, write fp16 g_ph.
// ---------------------------------------------------------------------------
__global__ void __launch_bounds__(256)
k_softmax()
{
    __shared__ float4 rowv[QQ / 4];   // 8 KB
    __shared__ float red[32];

    const float4* p = reinterpret_cast<const float4*>(g_t2 + (size_t)blockIdx.x * QQ);
    __half2* q = reinterpret_cast<__half2*>(g_ph + (size_t)blockIdx.x * QQ);
    const int tid = threadIdx.x;  // 256

    float m = -INFINITY;
#pragma unroll
    for (int i = tid; i < QQ / 4; i += 256) {
        float4 v = p[i];
        rowv[i] = v;
        m = fmaxf(m, fmaxf(fmaxf(v.x, v.y), fmaxf(v.z, v.w)));
    }
#pragma unroll
    for (int o = 16; o > 0; o >>= 1) m = fmaxf(m, __shfl_xor_sync(0xffffffffu, m, o));
    if ((tid & 31) == 0) red[tid >> 5] = m;
    __syncthreads();
    if (tid < 32) {
        float v = (tid < 8) ? red[tid] : -INFINITY;
#pragma unroll
        for (int o = 4; o > 0; o >>= 1) v = fmaxf(v, __shfl_xor_sync(0xffffffffu, v, o));
        red[tid] = v;
    }
    __syncthreads();
    m = red[0];
    __syncthreads();

    float sum = 0.f;
#pragma unroll
    for (int i = tid; i < QQ / 4; i += 256) {
        float4 v = rowv[i];
        v.x = __expf(v.x - m); v.y = __expf(v.y - m);
        v.z = __expf(v.z - m); v.w = __expf(v.w - m);
        rowv[i] = v;
        sum += v.x + v.y + v.z + v.w;
    }
#pragma unroll
    for (int o = 16; o > 0; o >>= 1) sum += __shfl_xor_sync(0xffffffffu, sum, o);
    if ((tid & 31) == 0) red[tid >> 5] = sum;
    __syncthreads();
    if (tid < 32) {
        float v = (tid < 8) ? red[tid] : 0.f;
#pragma unroll
        for (int o = 4; o > 0; o >>= 1) v += __shfl_xor_sync(0xffffffffu, v, o);
        red[tid] = v;
    }
    __syncthreads();
    const float inv = 1.0f / red[0];

#pragma unroll
    for (int i = tid; i < QQ / 4; i += 256) {
        float4 v = rowv[i];
        q[2 * i + 0] = __floats2half2_rn(v.x * inv, v.y * inv);
        q[2 * i + 1] = __floats2half2_rn(v.z * inv, v.w * inv);
    }
}

// ---------------------------------------------------------------------------
// Launcher
// ---------------------------------------------------------------------------
extern "C" void kernel_launch(void* const* d_in, const int* in_sizes, int n_in,
                              void* d_out, int out_size)
{
    const float* src  = (const float*)d_in[0];  // (B,S,D)
    const float* qry  = (const float*)d_in[1];  // (B,Q,D)
    const float* kern = (const float*)d_in[2];  // (Q,T)
    const float* wk   = (const float*)d_in[3];  // (D,Q)
    const float* wq   = (const float*)d_in[4];  // (S,D)
    float* out = (float*)d_out;                 // (B,Q,D)

    __half *srch, *qryh, *wqh, *wkTh, *kernTh;
    cudaGetSymbolAddress((void**)&srch, g_srch);
    cudaGetSymbolAddress((void**)&qryh, g_qryh);
    cudaGetSymbolAddress((void**)&wqh, g_wqh);
    cudaGetSymbolAddress((void**)&wkTh, g_wkTh);
    cudaGetSymbolAddress((void**)&kernTh, g_kernTh);

    cudaFuncSetAttribute(gemm_fatt, cudaFuncAttributeMaxDynamicSharedMemorySize, GSMEM_MK);
    cudaFuncSetAttribute(gemm_sim,  cudaFuncAttributeMaxDynamicSharedMemorySize, GSMEM_MK);
    cudaFuncSetAttribute(gemm_out,  cudaFuncAttributeMaxDynamicSharedMemorySize, GSMEM_KM);

    // 0) operand prep: merged fp16 conversion + merged weight transposes
    {
        const int thr_work = 4;
        const int nthr = (CVT_TOTAL + thr_work - 1) / thr_work;
        k_cvt_all<<<(nthr + 255) / 256, 256>>>(
            (const float4*)src, (uint2*)srch,
            (const float4*)qry, (uint2*)qryh,
            (const float4*)wq,  (uint2*)wqh);
    }
    k_transpose2<<<dim3(QQ / 32, DD / 32 + QQ / 32), dim3(32, 8)>>>(wk, wkTh, kern, kernTh);

    // 1) merged f_att: t1h = tanh(src@wk + wq@qry^T)
    gemm_fatt<<<dim3(QQ / BN, SS / BM, BB), 256, GSMEM_MK>>>();

    // 2) sim: t2 = t1h @ kernTh  (f32 out)
    gemm_sim<<<dim3(QQ / BN, SS / BM, BB), 256, GSMEM_MK>>>();

    // 3) softmax rows -> fp16 probs
    k_softmax<<<BB * SS, 256>>>();

    // 4) out = probs^T @ src
    gemm_out<<<dim3(DD / BN, QQ / BM, BB), 256, GSMEM_KM>>>(out);
}

// round 16
// speedup vs baseline: 1.0276x; 1.0276x over previous
#include <cuda_runtime.h>
#include <cuda_fp16.h>
#include <cstdint>
#include <math.h>

// Shapes (fixed)
#define BB 8
#define SS 2048
#define QQ 2048
#define DD 1024

// ---------------------------------------------------------------------------
// Scratch (device globals). fp16 operands, f32 where accumulation precision matters.
// ---------------------------------------------------------------------------
__device__ __half g_t1h[(size_t)BB * SS * QQ];        // tanh(f_att) fp16
__device__ float  g_t2[(size_t)BB * SS * QQ];         // sim (f32 for softmax)
__device__ __half g_ph[(size_t)BB * SS * QQ];         // softmax probs fp16
__device__ __half g_wkTh[(size_t)QQ * DD];            // wkT[q][d]
__device__ __half g_kernTh[(size_t)QQ * QQ];          // kernT[t][q]
__device__ __half g_srch[(size_t)BB * SS * DD];       // src fp16
__device__ __half g_qryh[(size_t)BB * QQ * DD];       // query fp16
__device__ __half g_wqh[(size_t)SS * DD];             // wq fp16

// ---------------------------------------------------------------------------
// PTX helpers (baseline PTX)
// ---------------------------------------------------------------------------
__device__ __forceinline__ uint32_t h2_as_u32(__half2 h) {
    uint32_t u;
    __builtin_memcpy(&u, &h, sizeof(u));
    return u;
}

__device__ __forceinline__ void mma_f16(float* d, const uint32_t* a, const uint32_t* b) {
    asm volatile(
        "mma.sync.aligned.m16n8k16.row.col.f32.f16.f16.f32 "
        "{%0,%1,%2,%3}, {%4,%5,%6,%7}, {%8,%9}, {%0,%1,%2,%3};\n"
        : "+f"(d[0]), "+f"(d[1]), "+f"(d[2]), "+f"(d[3])
        : "r"(a[0]), "r"(a[1]), "r"(a[2]), "r"(a[3]), "r"(b[0]), "r"(b[1]));
}

__device__ __forceinline__ void ldsm_x4(uint32_t* r, uint32_t saddr) {
    asm volatile("ldmatrix.sync.aligned.m8n8.x4.shared.b16 {%0,%1,%2,%3}, [%4];"
                 : "=r"(r[0]), "=r"(r[1]), "=r"(r[2]), "=r"(r[3])
                 : "r"(saddr));
}
__device__ __forceinline__ void ldsm_x4_t(uint32_t* r, uint32_t saddr) {
    asm volatile("ldmatrix.sync.aligned.m8n8.x4.trans.shared.b16 {%0,%1,%2,%3}, [%4];"
                 : "=r"(r[0]), "=r"(r[1]), "=r"(r[2]), "=r"(r[3])
                 : "r"(saddr));
}

__device__ __forceinline__ void cp_async16(uint32_t smem_addr, const void* gptr) {
    asm volatile("cp.async.cg.shared.global [%0], [%1], 16;"
                 :: "r"(smem_addr), "l"(gptr));
}
#define CP_COMMIT() asm volatile("cp.async.commit_group;" ::: "memory")
#define CP_WAIT1()  asm volatile("cp.async.wait_group 1;" ::: "memory")

// ---------------------------------------------------------------------------
// Geometry (proven): 128x128 CTA tile, BK=64 halves, 256 threads,
// 8 warps = 4(M) x 2(N), warp tile 32x64. 3-stage cp.async, wait_group 1.
// ---------------------------------------------------------------------------
#define BM 128
#define BN 128
#define BK 64
#define LDTH 72                             // MK row stride (halves): 144B, LDSM conflict-free
#define LDMH 136                            // KM row stride (halves): 272B, conflict-free
#define STG_MK (BM * LDTH * 2)              // 18432 B / operand / stage
#define GSMEM_MK (6 * STG_MK)               // 110592 B (3 stages x 2 operands)
#define STG_KM (BK * LDMH * 2)              // 17408 B
#define GSMEM_KM (6 * STG_KM)               // 104448 B

// rotating 3-stage offset (no modulo)
#define ROT3(off, stg) do { (off) += (stg); if ((off) == 3u * (stg)) (off) = 0u; } while (0)

// per-thread LDSM source byte offsets within one MK stage (32x64 warp tile)
struct LdsmOffs { uint32_t a[2]; uint32_t b[4]; };

__device__ __forceinline__ LdsmOffs make_offs_mk(int warp_row, int warp_col, int lane) {
    LdsmOffs o;
    const int sel = lane >> 3, rin = lane & 7;
#pragma unroll
    for (int i = 0; i < 2; i++) {
        int r = warp_row * 32 + i * 16 + (sel & 1) * 8 + rin;   // m row
        int c = (sel >> 1) * 8;                                 // k halves
        o.a[i] = (uint32_t)((r * LDTH + c) * 2);
    }
#pragma unroll
    for (int jp = 0; jp < 4; jp++) {
        int n = warp_col * 64 + jp * 16 + (sel >> 1) * 8 + rin; // n row
        int c = (sel & 1) * 8;
        o.b[jp] = (uint32_t)((n * LDTH + c) * 2);
    }
    return o;
}

// one k16 step (MK): 6 LDSM.x4 + 16 MMA
__device__ __forceinline__ void mma_step_mk(float acc[2][8][4],
                                            uint32_t aBase, uint32_t bBase,
                                            const LdsmOffs& o, int ks) {
    const uint32_t kadd = ks * 32;   // 16 halves = 32 B
    uint32_t afr[2][4];
    ldsm_x4(afr[0], aBase + o.a[0] + kadd);
    ldsm_x4(afr[1], aBase + o.a[1] + kadd);
    uint32_t bfr[4][4];
#pragma unroll
    for (int jp = 0; jp < 4; jp++)
        ldsm_x4(bfr[jp], bBase + o.b[jp] + kadd);
#pragma unroll
    for (int i = 0; i < 2; i++)
#pragma unroll
        for (int j = 0; j < 8; j++)
            mma_f16(acc[i][j], afr[i], &bfr[j >> 1][(j & 1) * 2]);
}

// ============================================================================
// Kernel A: merged f_att GEMM (MK). K=2048 as two 1024 halves:
//   tiles 0..15: A=srch[b], B=wkTh ; tiles 16..31: A=wqh, B=qryh[b]
// Epilogue: tanhf -> fp16 g_t1h.
// ============================================================================
__global__ void __launch_bounds__(256, 2)
gemm_fatt()
{
    extern __shared__ uint32_t smem[];
    const uint32_t sBase = (uint32_t)__cvta_generic_to_shared(smem);
    const uint32_t asBase = sBase;
    const uint32_t bsBase = sBase + 3 * STG_MK;

    const int tid = threadIdx.x;
    const int wid = tid >> 5;
    const int lane = tid & 31;
    const int warp_row = wid >> 1;
    const int warp_col = wid & 1;

    const int b  = blockIdx.z;
    const int m0 = blockIdx.y * BM;
    const int n0 = blockIdx.x * BN;

    const __half* a_half[2] = { g_srch + (size_t)b * SS * DD + (size_t)m0 * DD,
                                g_wqh  + (size_t)m0 * DD };
    const __half* b_half[2] = { g_wkTh + (size_t)n0 * DD,
                                g_qryh + (size_t)b * QQ * DD + (size_t)n0 * DD };

    const int l_row = tid >> 3;          // 0..31
    const int l_c8  = (tid & 7) * 8;     // halves 0..56

    uint32_t wOff[4];
#pragma unroll
    for (int u = 0; u < 4; u++)
        wOff[u] = (uint32_t)(((l_row + 32 * u) * LDTH + l_c8) * 2);

    const LdsmOffs offs = make_offs_mk(warp_row, warp_col, lane);

    float acc[2][8][4];
#pragma unroll
    for (int i = 0; i < 2; i++)
#pragma unroll
        for (int j = 0; j < 8; j++)
#pragma unroll
            for (int r = 0; r < 4; r++) acc[i][j][r] = 0.f;

    const int ntiles = 2048 / BK;   // 32 (16 per half)

    // prologue: tiles 0,1 (both half 0)
#pragma unroll
    for (int p = 0; p < 2; p++) {
        const int k0 = p * BK;
        const __half* ap = a_half[0] + (size_t)l_row * DD + k0 + l_c8;
        const __half* bp = b_half[0] + (size_t)l_row * DD + k0 + l_c8;
        const uint32_t so = (uint32_t)p * STG_MK;
#pragma unroll
        for (int u = 0; u < 4; u++) {
            cp_async16(asBase + so + wOff[u], ap + (size_t)(32 * u) * DD);
            cp_async16(bsBase + so + wOff[u], bp + (size_t)(32 * u) * DD);
        }
        CP_COMMIT();
    }

    uint32_t co = 0;                       // compute stage offset
    uint32_t po = 2u * STG_MK;             // prefetch stage offset
    for (int t = 0; t < ntiles; t++) {
        CP_WAIT1();
        __syncthreads();

        if (t + 2 < ntiles) {
            const int tt = t + 2;
            const int h  = tt >> 4;
            const int k0 = (tt & 15) * BK;
            const __half* ap = a_half[h] + (size_t)l_row * DD + k0 + l_c8;
            const __half* bp = b_half[h] + (size_t)l_row * DD + k0 + l_c8;
#pragma unroll
            for (int u = 0; u < 4; u++) {
                cp_async16(asBase + po + wOff[u], ap + (size_t)(32 * u) * DD);
                cp_async16(bsBase + po + wOff[u], bp + (size_t)(32 * u) * DD);
            }
            CP_COMMIT();
        }
        ROT3(po, (uint32_t)STG_MK);

#pragma unroll
        for (int ks = 0; ks < 4; ks++)
            mma_step_mk(acc, asBase + co, bsBase + co, offs, ks);
        ROT3(co, (uint32_t)STG_MK);
    }

    __half* Cb = g_t1h + (size_t)b * SS * QQ;
#pragma unroll
    for (int i = 0; i < 2; i++) {
        const int row0 = m0 + warp_row * 32 + i * 16 + (lane >> 2);
#pragma unroll
        for (int j = 0; j < 8; j++) {
            const int col = n0 + warp_col * 64 + j * 8 + 2 * (lane & 3);
#pragma unroll
            for (int r = 0; r < 2; r++) {
                const size_t off = (size_t)(row0 + r * 8) * QQ + col;
                __half2 h = __floats2half2_rn(tanhf(acc[i][j][r * 2 + 0]),
                                              tanhf(acc[i][j][r * 2 + 1]));
                *reinterpret_cast<__half2*>(Cb + off) = h;
            }
        }
    }
}

// ============================================================================
// Kernel B: sim GEMM (MK). C[b][m][n] = sum_k t1h[b][m][k] * kernTh[n][k], K=2048.
// ============================================================================
__global__ void __launch_bounds__(256, 2)
gemm_sim()
{
    extern __shared__ uint32_t smem[];
    const uint32_t sBase = (uint32_t)__cvta_generic_to_shared(smem);
    const uint32_t asBase = sBase;
    const uint32_t bsBase = sBase + 3 * STG_MK;

    const int tid = threadIdx.x;
    const int wid = tid >> 5;
    const int lane = tid & 31;
    const int warp_row = wid >> 1;
    const int warp_col = wid & 1;

    const int b  = blockIdx.z;
    const int m0 = blockIdx.y * BM;
    const int n0 = blockIdx.x * BN;

    const __half* Ab = g_t1h + (size_t)b * SS * QQ + (size_t)m0 * QQ;
    const __half* Bb = g_kernTh + (size_t)n0 * QQ;

    const int l_row = tid >> 3;
    const int l_c8  = (tid & 7) * 8;

    uint32_t wOff[4];
#pragma unroll
    for (int u = 0; u < 4; u++)
        wOff[u] = (uint32_t)(((l_row + 32 * u) * LDTH + l_c8) * 2);

    const LdsmOffs offs = make_offs_mk(warp_row, warp_col, lane);

    float acc[2][8][4];
#pragma unroll
    for (int i = 0; i < 2; i++)
#pragma unroll
        for (int j = 0; j < 8; j++)
#pragma unroll
            for (int r = 0; r < 4; r++) acc[i][j][r] = 0.f;

    const int ntiles = QQ / BK;   // 32

#pragma unroll
    for (int p = 0; p < 2; p++) {
        const int k0 = p * BK;
        const __half* ap = Ab + (size_t)l_row * QQ + k0 + l_c8;
        const __half* bp = Bb + (size_t)l_row * QQ + k0 + l_c8;
        const uint32_t so = (uint32_t)p * STG_MK;
#pragma unroll
        for (int u = 0; u < 4; u++) {
            cp_async16(asBase + so + wOff[u], ap + (size_t)(32 * u) * QQ);
            cp_async16(bsBase + so + wOff[u], bp + (size_t)(32 * u) * QQ);
        }
        CP_COMMIT();
    }

    uint32_t co = 0;
    uint32_t po = 2u * STG_MK;
    for (int t = 0; t < ntiles; t++) {
        CP_WAIT1();
        __syncthreads();

        if (t + 2 < ntiles) {
            const int k0 = (t + 2) * BK;
            const __half* ap = Ab + (size_t)l_row * QQ + k0 + l_c8;
            const __half* bp = Bb + (size_t)l_row * QQ + k0 + l_c8;
#pragma unroll
            for (int u = 0; u < 4; u++) {
                cp_async16(asBase + po + wOff[u], ap + (size_t)(32 * u) * QQ);
                cp_async16(bsBase + po + wOff[u], bp + (size_t)(32 * u) * QQ);
            }
            CP_COMMIT();
        }
        ROT3(po, (uint32_t)STG_MK);

#pragma unroll
        for (int ks = 0; ks < 4; ks++)
            mma_step_mk(acc, asBase + co, bsBase + co, offs, ks);
        ROT3(co, (uint32_t)STG_MK);
    }

    float* Cb = g_t2 + (size_t)b * SS * QQ;
#pragma unroll
    for (int i = 0; i < 2; i++) {
        const int row0 = m0 + warp_row * 32 + i * 16 + (lane >> 2);
#pragma unroll
        for (int j = 0; j < 8; j++) {
            const int col = n0 + warp_col * 64 + j * 8 + 2 * (lane & 3);
#pragma unroll
            for (int r = 0; r < 2; r++) {
                const size_t off = (size_t)(row0 + r * 8) * QQ + col;
                float2 v;
                v.x = acc[i][j][r * 2 + 0];
                v.y = acc[i][j][r * 2 + 1];
                *reinterpret_cast<float2*>(Cb + off) = v;
            }
        }
    }
}

// ============================================================================
// Kernel C: out[b][q][d] = sum_s ph[b][s][q] * srch[b][s][d]  (KM layout, K=s)
// ldmatrix.trans both operands. BK=64, 3-stage.
// ============================================================================
__global__ void __launch_bounds__(256, 2)
gemm_out(float* __restrict__ C)
{
    extern __shared__ uint32_t smem[];
    const uint32_t sBase = (uint32_t)__cvta_generic_to_shared(smem);
    const uint32_t asBase = sBase;
    const uint32_t bsBase = sBase + 3 * STG_KM;

    const int tid = threadIdx.x;
    const int wid = tid >> 5;
    const int lane = tid & 31;
    const int warp_row = wid >> 1;
    const int warp_col = wid & 1;

    const int b  = blockIdx.z;
    const int m0 = blockIdx.y * BM;   // q
    const int n0 = blockIdx.x * BN;   // d

    const __half* Ab = g_ph + (size_t)b * SS * QQ + m0;
    const __half* Bb = g_srch + (size_t)b * SS * DD + n0;

    const int lk = tid >> 3;          // 0..31
    const int lc = (tid & 7) * 8;     // halves 0..56

    uint32_t w[4];
    int wr[4], wc[4];
#pragma unroll
    for (int u = 0; u < 4; u++) {
        wr[u] = lk + 32 * (u >> 1);
        wc[u] = lc + 64 * (u & 1);
        w[u] = (uint32_t)((wr[u] * LDMH + wc[u]) * 2);
    }

    const int sel = lane >> 3, rin = lane & 7;
    uint32_t oa[2], ob[4];
#pragma unroll
    for (int i = 0; i < 2; i++)
        oa[i] = (uint32_t)((((sel >> 1) * 8 + rin) * LDMH
                           + warp_row * 32 + i * 16 + (sel & 1) * 8) * 2);
#pragma unroll
    for (int jp = 0; jp < 4; jp++)
        ob[jp] = (uint32_t)((((sel & 1) * 8 + rin) * LDMH
                           + warp_col * 64 + jp * 16 + (sel >> 1) * 8) * 2);

    float acc[2][8][4];
#pragma unroll
    for (int i = 0; i < 2; i++)
#pragma unroll
        for (int j = 0; j < 8; j++)
#pragma unroll
            for (int r = 0; r < 4; r++) acc[i][j][r] = 0.f;

    const int ntiles = SS / BK;   // 32

#pragma unroll
    for (int p = 0; p < 2; p++) {
        const int k0 = p * BK;
        const uint32_t so = (uint32_t)p * STG_KM;
#pragma unroll
        for (int u = 0; u < 4; u++) {
            cp_async16(asBase + so + w[u], Ab + (size_t)(k0 + wr[u]) * QQ + wc[u]);
            cp_async16(bsBase + so + w[u], Bb + (size_t)(k0 + wr[u]) * DD + wc[u]);
        }
        CP_COMMIT();
    }

    uint32_t co = 0;
    uint32_t po = 2u * STG_KM;
    for (int t = 0; t < ntiles; t++) {
        CP_WAIT1();
        __syncthreads();

        if (t + 2 < ntiles) {
            const int k0 = (t + 2) * BK;
#pragma unroll
            for (int u = 0; u < 4; u++) {
                cp_async16(asBase + po + w[u], Ab + (size_t)(k0 + wr[u]) * QQ + wc[u]);
                cp_async16(bsBase + po + w[u], Bb + (size_t)(k0 + wr[u]) * DD + wc[u]);
            }
            CP_COMMIT();
        }
        ROT3(po, (uint32_t)STG_KM);

        const uint32_t aB = asBase + co;
        const uint32_t bB = bsBase + co;

#pragma unroll
        for (int ks = 0; ks < 4; ks++) {
            const uint32_t kadd = (uint32_t)(ks * 16 * LDMH * 2);
            uint32_t afr[2][4];
            ldsm_x4_t(afr[0], aB + oa[0] + kadd);
            ldsm_x4_t(afr[1], aB + oa[1] + kadd);
            uint32_t bfr[4][4];
#pragma unroll
            for (int jp = 0; jp < 4; jp++)
                ldsm_x4_t(bfr[jp], bB + ob[jp] + kadd);
#pragma unroll
            for (int i = 0; i < 2; i++)
#pragma unroll
                for (int j = 0; j < 8; j++)
                    mma_f16(acc[i][j], afr[i], &bfr[j >> 1][(j & 1) * 2]);
        }
        ROT3(co, (uint32_t)STG_KM);
    }

    float* Cb = C + (size_t)b * QQ * DD;
#pragma unroll
    for (int i = 0; i < 2; i++) {
        const int row0 = m0 + warp_row * 32 + i * 16 + (lane >> 2);
#pragma unroll
        for (int j = 0; j < 8; j++) {
            const int col = n0 + warp_col * 64 + j * 8 + 2 * (lane & 3);
#pragma unroll
            for (int r = 0; r < 2; r++) {
                const size_t off = (size_t)(row0 + r * 8) * DD + col;
                float2 v;
                v.x = acc[i][j][r * 2 + 0];
                v.y = acc[i][j][r * 2 + 1];
                *reinterpret_cast<float2*>(Cb + off) = v;
            }
        }
    }
}

// ---------------------------------------------------------------------------
// Merged elementwise f32 -> fp16 over three buffers (round-14 form: one
// float4 per thread, single branch, no streaming hints)
// ---------------------------------------------------------------------------
#define CVT_N0 ((BB * SS * DD) / 4)   // src
#define CVT_N1 ((BB * QQ * DD) / 4)   // qry
#define CVT_N2 ((SS * DD) / 4)        // wq
#define CVT_TOTAL (CVT_N0 + CVT_N1 + CVT_N2)

__global__ void k_cvt_all(const float4* __restrict__ src, uint2* __restrict__ srch,
                          const float4* __restrict__ qry, uint2* __restrict__ qryh,
                          const float4* __restrict__ wq,  uint2* __restrict__ wqh)
{
    int i = blockIdx.x * blockDim.x + threadIdx.x;
    if (i >= CVT_TOTAL) return;
    const float4* in;
    uint2* out;
    int idx;
    if (i < CVT_N0)                { in = src; out = srch; idx = i; }
    else if (i < CVT_N0 + CVT_N1)  { in = qry; out = qryh; idx = i - CVT_N0; }
    else                           { in = wq;  out = wqh;  idx = i - CVT_N0 - CVT_N1; }
    float4 v = in[idx];
    uint2 o;
    o.x = h2_as_u32(__floats2half2_rn(v.x, v.y));
    o.y = h2_as_u32(__floats2half2_rn(v.z, v.w));
    out[idx] = o;
}

// ---------------------------------------------------------------------------
// Merged tiled transpose f32 -> fp16 for wk (D x Q) and kern (Q x Q).
// ---------------------------------------------------------------------------
__global__ void k_transpose2(const float* __restrict__ wk, __half* __restrict__ wkT,
                             const float* __restrict__ kern, __half* __restrict__ kernT)
{
    __shared__ float tile[32][33];
    const float* in;
    __half* out;
    int R, C, r0;
    if (blockIdx.y < DD / 32) {
        in = wk; out = wkT; R = DD; C = QQ; r0 = blockIdx.y * 32;
    } else {
        in = kern; out = kernT; R = QQ; C = QQ; r0 = (blockIdx.y - DD / 32) * 32;
    }
    const int c0 = blockIdx.x * 32;

#pragma unroll
    for (int i = threadIdx.y; i < 32; i += 8)
        tile[i][threadIdx.x] = in[(size_t)(r0 + i) * C + c0 + threadIdx.x];
    __syncthreads();
#pragma unroll
    for (int i = threadIdx.y; i < 32; i += 8)
        out[(size_t)(c0 + i) * R + r0 + threadIdx.x] = __float2half_rn(tile[threadIdx.x][i]);
}

// ---------------------------------------------------------------------------
// SMEM-resident row softmax: read f32 g_t2, write fp16 g_ph.
// ---------------------------------------------------------------------------
__global__ void __launch_bounds__(256)
k_softmax()
{
    __shared__ float4 rowv[QQ / 4];   // 8 KB
    __shared__ float red[32];

    const float4* p = reinterpret_cast<const float4*>(g_t2 + (size_t)blockIdx.x * QQ);
    __half2* q = reinterpret_cast<__half2*>(g_ph + (size_t)blockIdx.x * QQ);
    const int tid = threadIdx.x;  // 256

    float m = -INFINITY;
#pragma unroll
    for (int i = tid; i < QQ / 4; i += 256) {
        float4 v = p[i];
        rowv[i] = v;
        m = fmaxf(m, fmaxf(fmaxf(v.x, v.y), fmaxf(v.z, v.w)));
    }
#pragma unroll
    for (int o = 16; o > 0; o >>= 1) m = fmaxf(m, __shfl_xor_sync(0xffffffffu, m, o));
    if ((tid & 31) == 0) red[tid >> 5] = m;
    __syncthreads();
    if (tid < 32) {
        float v = (tid < 8) ? red[tid] : -INFINITY;
#pragma unroll
        for (int o = 4; o > 0; o >>= 1) v = fmaxf(v, __shfl_xor_sync(0xffffffffu, v, o));
        red[tid] = v;
    }
    __syncthreads();
    m = red[0];
    __syncthreads();

    float sum = 0.f;
#pragma unroll
    for (int i = tid; i < QQ / 4; i += 256) {
        float4 v = rowv[i];
        v.x = __expf(v.x - m); v.y = __expf(v.y - m);
        v.z = __expf(v.z - m); v.w = __expf(v.w - m);
        rowv[i] = v;
        sum += v.x + v.y + v.z + v.w;
    }
#pragma unroll
    for (int o = 16; o > 0; o >>= 1) sum += __shfl_xor_sync(0xffffffffu, sum, o);
    if ((tid & 31) == 0) red[tid >> 5] = sum;
    __syncthreads();
    if (tid < 32) {
        float v = (tid < 8) ? red[tid] : 0.f;
#pragma unroll
        for (int o = 4; o > 0; o >>= 1) v += __shfl_xor_sync(0xffffffffu, v, o);
        red[tid] = v;
    }
    __syncthreads();
    const float inv = 1.0f / red[0];

#pragma unroll
    for (int i = tid; i < QQ / 4; i += 256) {
        float4 v = rowv[i];
        q[2 * i + 0] = __floats2half2_rn(v.x * inv, v.y * inv);
        q[2 * i + 1] = __floats2half2_rn(v.z * inv, v.w * inv);
    }
}

// ---------------------------------------------------------------------------
// Launcher
// ---------------------------------------------------------------------------
extern "C" void kernel_launch(void* const* d_in, const int* in_sizes, int n_in,
                              void* d_out, int out_size)
{
    const float* src  = (const float*)d_in[0];  // (B,S,D)
    const float* qry  = (const float*)d_in[1];  // (B,Q,D)
    const float* kern = (const float*)d_in[2];  // (Q,T)
    const float* wk   = (const float*)d_in[3];  // (D,Q)
    const float* wq   = (const float*)d_in[4];  // (S,D)
    float* out = (float*)d_out;                 // (B,Q,D)

    __half *srch, *qryh, *wqh, *wkTh, *kernTh;
    cudaGetSymbolAddress((void**)&srch, g_srch);
    cudaGetSymbolAddress((void**)&qryh, g_qryh);
    cudaGetSymbolAddress((void**)&wqh, g_wqh);
    cudaGetSymbolAddress((void**)&wkTh, g_wkTh);
    cudaGetSymbolAddress((void**)&kernTh, g_kernTh);

    cudaFuncSetAttribute(gemm_fatt, cudaFuncAttributeMaxDynamicSharedMemorySize, GSMEM_MK);
    cudaFuncSetAttribute(gemm_sim,  cudaFuncAttributeMaxDynamicSharedMemorySize, GSMEM_MK);
    cudaFuncSetAttribute(gemm_out,  cudaFuncAttributeMaxDynamicSharedMemorySize, GSMEM_KM);

    // 0) operand prep: merged fp16 conversion (1 float4/thread) + merged transposes
    k_cvt_all<<<(CVT_TOTAL + 255) / 256, 256>>>(
        (const float4*)src, (uint2*)srch,
        (const float4*)qry, (uint2*)qryh,
        (const float4*)wq,  (uint2*)wqh);
    k_transpose2<<<dim3(QQ / 32, DD / 32 + QQ / 32), dim3(32, 8)>>>(wk, wkTh, kern, kernTh);

    // 1) merged f_att: t1h = tanh(src@wk + wq@qry^T)
    gemm_fatt<<<dim3(QQ / BN, SS / BM, BB), 256, GSMEM_MK>>>();

    // 2) sim: t2 = t1h @ kernTh  (f32 out)
    gemm_sim<<<dim3(QQ / BN, SS / BM, BB), 256, GSMEM_MK>>>();

    // 3) softmax rows -> fp16 probs
    k_softmax<<<BB * SS, 256>>>();

    // 4) out = probs^T @ src
    gemm_out<<<dim3(DD / BN, QQ / BM, BB), 256, GSMEM_KM>>>(out);
}

// round 17
// speedup vs baseline: 1.0315x; 1.0038x over previous
#include <cuda_runtime.h>
#include <cuda_fp16.h>
#include <cstdint>
#include <math.h>

// Shapes (fixed)
#define BB 8
#define SS 2048
#define QQ 2048
#define DD 1024

// ---------------------------------------------------------------------------
// Scratch (device globals). fp16 operands everywhere; f32 accumulation in-reg.
// ---------------------------------------------------------------------------
__device__ __half g_t1h[(size_t)BB * SS * QQ];        // tanh(f_att) fp16
__device__ __half g_ph[(size_t)BB * SS * QQ];         // sim logits -> softmax probs (in-place, fp16)
__device__ __half g_wkTh[(size_t)QQ * DD];            // wkT[q][d]
__device__ __half g_kernTh[(size_t)QQ * QQ];          // kernT[t][q]
__device__ __half g_srch[(size_t)BB * SS * DD];       // src fp16
__device__ __half g_qryh[(size_t)BB * QQ * DD];       // query fp16
__device__ __half g_wqh[(size_t)SS * DD];             // wq fp16

// ---------------------------------------------------------------------------
// PTX helpers (baseline PTX)
// ---------------------------------------------------------------------------
__device__ __forceinline__ uint32_t h2_as_u32(__half2 h) {
    uint32_t u;
    __builtin_memcpy(&u, &h, sizeof(u));
    return u;
}

__device__ __forceinline__ void mma_f16(float* d, const uint32_t* a, const uint32_t* b) {
    asm volatile(
        "mma.sync.aligned.m16n8k16.row.col.f32.f16.f16.f32 "
        "{%0,%1,%2,%3}, {%4,%5,%6,%7}, {%8,%9}, {%0,%1,%2,%3};\n"
        : "+f"(d[0]), "+f"(d[1]), "+f"(d[2]), "+f"(d[3])
        : "r"(a[0]), "r"(a[1]), "r"(a[2]), "r"(a[3]), "r"(b[0]), "r"(b[1]));
}

__device__ __forceinline__ void ldsm_x4(uint32_t* r, uint32_t saddr) {
    asm volatile("ldmatrix.sync.aligned.m8n8.x4.shared.b16 {%0,%1,%2,%3}, [%4];"
                 : "=r"(r[0]), "=r"(r[1]), "=r"(r[2]), "=r"(r[3])
                 : "r"(saddr));
}
__device__ __forceinline__ void ldsm_x4_t(uint32_t* r, uint32_t saddr) {
    asm volatile("ldmatrix.sync.aligned.m8n8.x4.trans.shared.b16 {%0,%1,%2,%3}, [%4];"
                 : "=r"(r[0]), "=r"(r[1]), "=r"(r[2]), "=r"(r[3])
                 : "r"(saddr));
}

__device__ __forceinline__ void cp_async16(uint32_t smem_addr, const void* gptr) {
    asm volatile("cp.async.cg.shared.global [%0], [%1], 16;"
                 :: "r"(smem_addr), "l"(gptr));
}
#define CP_COMMIT() asm volatile("cp.async.commit_group;" ::: "memory")
#define CP_WAIT1()  asm volatile("cp.async.wait_group 1;" ::: "memory")

// ---------------------------------------------------------------------------
// Geometry (proven): 128x128 CTA tile, BK=64 halves, 256 threads,
// 8 warps = 4(M) x 2(N), warp tile 32x64. 3-stage cp.async, wait_group 1.
// ---------------------------------------------------------------------------
#define BM 128
#define BN 128
#define BK 64
#define LDTH 72                             // MK row stride (halves): 144B, LDSM conflict-free
#define LDMH 136                            // KM row stride (halves): 272B, conflict-free
#define STG_MK (BM * LDTH * 2)              // 18432 B / operand / stage
#define GSMEM_MK (6 * STG_MK)               // 110592 B (3 stages x 2 operands)
#define STG_KM (BK * LDMH * 2)              // 17408 B
#define GSMEM_KM (6 * STG_KM)               // 104448 B

// rotating 3-stage offset (no modulo)
#define ROT3(off, stg) do { (off) += (stg); if ((off) == 3u * (stg)) (off) = 0u; } while (0)

// per-thread LDSM source byte offsets within one MK stage (32x64 warp tile)
struct LdsmOffs { uint32_t a[2]; uint32_t b[4]; };

__device__ __forceinline__ LdsmOffs make_offs_mk(int warp_row, int warp_col, int lane) {
    LdsmOffs o;
    const int sel = lane >> 3, rin = lane & 7;
#pragma unroll
    for (int i = 0; i < 2; i++) {
        int r = warp_row * 32 + i * 16 + (sel & 1) * 8 + rin;   // m row
        int c = (sel >> 1) * 8;                                 // k halves
        o.a[i] = (uint32_t)((r * LDTH + c) * 2);
    }
#pragma unroll
    for (int jp = 0; jp < 4; jp++) {
        int n = warp_col * 64 + jp * 16 + (sel >> 1) * 8 + rin; // n row
        int c = (sel & 1) * 8;
        o.b[jp] = (uint32_t)((n * LDTH + c) * 2);
    }
    return o;
}

// one k16 step (MK): 6 LDSM.x4 + 16 MMA
__device__ __forceinline__ void mma_step_mk(float acc[2][8][4],
                                            uint32_t aBase, uint32_t bBase,
                                            const LdsmOffs& o, int ks) {
    const uint32_t kadd = ks * 32;   // 16 halves = 32 B
    uint32_t afr[2][4];
    ldsm_x4(afr[0], aBase + o.a[0] + kadd);
    ldsm_x4(afr[1], aBase + o.a[1] + kadd);
    uint32_t bfr[4][4];
#pragma unroll
    for (int jp = 0; jp < 4; jp++)
        ldsm_x4(bfr[jp], bBase + o.b[jp] + kadd);
#pragma unroll
    for (int i = 0; i < 2; i++)
#pragma unroll
        for (int j = 0; j < 8; j++)
            mma_f16(acc[i][j], afr[i], &bfr[j >> 1][(j & 1) * 2]);
}

// ============================================================================
// Kernel A: merged f_att GEMM (MK). K=2048 as two 1024 halves:
//   tiles 0..15: A=srch[b], B=wkTh ; tiles 16..31: A=wqh, B=qryh[b]
// Epilogue: tanhf -> fp16 g_t1h.
// ============================================================================
__global__ void __launch_bounds__(256, 2)
gemm_fatt()
{
    extern __shared__ uint32_t smem[];
    const uint32_t sBase = (uint32_t)__cvta_generic_to_shared(smem);
    const uint32_t asBase = sBase;
    const uint32_t bsBase = sBase + 3 * STG_MK;

    const int tid = threadIdx.x;
    const int wid = tid >> 5;
    const int lane = tid & 31;
    const int warp_row = wid >> 1;
    const int warp_col = wid & 1;

    const int b  = blockIdx.z;
    const int m0 = blockIdx.y * BM;
    const int n0 = blockIdx.x * BN;

    const __half* a_half[2] = { g_srch + (size_t)b * SS * DD + (size_t)m0 * DD,
                                g_wqh  + (size_t)m0 * DD };
    const __half* b_half[2] = { g_wkTh + (size_t)n0 * DD,
                                g_qryh + (size_t)b * QQ * DD + (size_t)n0 * DD };

    const int l_row = tid >> 3;          // 0..31
    const int l_c8  = (tid & 7) * 8;     // halves 0..56

    uint32_t wOff[4];
#pragma unroll
    for (int u = 0; u < 4; u++)
        wOff[u] = (uint32_t)(((l_row + 32 * u) * LDTH + l_c8) * 2);

    const LdsmOffs offs = make_offs_mk(warp_row, warp_col, lane);

    float acc[2][8][4];
#pragma unroll
    for (int i = 0; i < 2; i++)
#pragma unroll
        for (int j = 0; j < 8; j++)
#pragma unroll
            for (int r = 0; r < 4; r++) acc[i][j][r] = 0.f;

    const int ntiles = 2048 / BK;   // 32 (16 per half)

    // prologue: tiles 0,1 (both half 0)
#pragma unroll
    for (int p = 0; p < 2; p++) {
        const int k0 = p * BK;
        const __half* ap = a_half[0] + (size_t)l_row * DD + k0 + l_c8;
        const __half* bp = b_half[0] + (size_t)l_row * DD + k0 + l_c8;
        const uint32_t so = (uint32_t)p * STG_MK;
#pragma unroll
        for (int u = 0; u < 4; u++) {
            cp_async16(asBase + so + wOff[u], ap + (size_t)(32 * u) * DD);
            cp_async16(bsBase + so + wOff[u], bp + (size_t)(32 * u) * DD);
        }
        CP_COMMIT();
    }

    uint32_t co = 0;                       // compute stage offset
    uint32_t po = 2u * STG_MK;             // prefetch stage offset
    for (int t = 0; t < ntiles; t++) {
        CP_WAIT1();
        __syncthreads();

        if (t + 2 < ntiles) {
            const int tt = t + 2;
            const int h  = tt >> 4;
            const int k0 = (tt & 15) * BK;
            const __half* ap = a_half[h] + (size_t)l_row * DD + k0 + l_c8;
            const __half* bp = b_half[h] + (size_t)l_row * DD + k0 + l_c8;
#pragma unroll
            for (int u = 0; u < 4; u++) {
                cp_async16(asBase + po + wOff[u], ap + (size_t)(32 * u) * DD);
                cp_async16(bsBase + po + wOff[u], bp + (size_t)(32 * u) * DD);
            }
            CP_COMMIT();
        }
        ROT3(po, (uint32_t)STG_MK);

#pragma unroll
        for (int ks = 0; ks < 4; ks++)
            mma_step_mk(acc, asBase + co, bsBase + co, offs, ks);
        ROT3(co, (uint32_t)STG_MK);
    }

    __half* Cb = g_t1h + (size_t)b * SS * QQ;
#pragma unroll
    for (int i = 0; i < 2; i++) {
        const int row0 = m0 + warp_row * 32 + i * 16 + (lane >> 2);
#pragma unroll
        for (int j = 0; j < 8; j++) {
            const int col = n0 + warp_col * 64 + j * 8 + 2 * (lane & 3);
#pragma unroll
            for (int r = 0; r < 2; r++) {
                const size_t off = (size_t)(row0 + r * 8) * QQ + col;
                __half2 h = __floats2half2_rn(tanhf(acc[i][j][r * 2 + 0]),
                                              tanhf(acc[i][j][r * 2 + 1]));
                *reinterpret_cast<__half2*>(Cb + off) = h;
            }
        }
    }
}

// ============================================================================
// Kernel B: sim GEMM (MK). logits[b][m][n] = sum_k t1h[b][m][k] * kernTh[n][k].
// Epilogue: fp16 store -> g_ph (softmax runs in-place on it).
// ============================================================================
__global__ void __launch_bounds__(256, 2)
gemm_sim()
{
    extern __shared__ uint32_t smem[];
    const uint32_t sBase = (uint32_t)__cvta_generic_to_shared(smem);
    const uint32_t asBase = sBase;
    const uint32_t bsBase = sBase + 3 * STG_MK;

    const int tid = threadIdx.x;
    const int wid = tid >> 5;
    const int lane = tid & 31;
    const int warp_row = wid >> 1;
    const int warp_col = wid & 1;

    const int b  = blockIdx.z;
    const int m0 = blockIdx.y * BM;
    const int n0 = blockIdx.x * BN;

    const __half* Ab = g_t1h + (size_t)b * SS * QQ + (size_t)m0 * QQ;
    const __half* Bb = g_kernTh + (size_t)n0 * QQ;

    const int l_row = tid >> 3;
    const int l_c8  = (tid & 7) * 8;

    uint32_t wOff[4];
#pragma unroll
    for (int u = 0; u < 4; u++)
        wOff[u] = (uint32_t)(((l_row + 32 * u) * LDTH + l_c8) * 2);

    const LdsmOffs offs = make_offs_mk(warp_row, warp_col, lane);

    float acc[2][8][4];
#pragma unroll
    for (int i = 0; i < 2; i++)
#pragma unroll
        for (int j = 0; j < 8; j++)
#pragma unroll
            for (int r = 0; r < 4; r++) acc[i][j][r] = 0.f;

    const int ntiles = QQ / BK;   // 32

#pragma unroll
    for (int p = 0; p < 2; p++) {
        const int k0 = p * BK;
        const __half* ap = Ab + (size_t)l_row * QQ + k0 + l_c8;
        const __half* bp = Bb + (size_t)l_row * QQ + k0 + l_c8;
        const uint32_t so = (uint32_t)p * STG_MK;
#pragma unroll
        for (int u = 0; u < 4; u++) {
            cp_async16(asBase + so + wOff[u], ap + (size_t)(32 * u) * QQ);
            cp_async16(bsBase + so + wOff[u], bp + (size_t)(32 * u) * QQ);
        }
        CP_COMMIT();
    }

    uint32_t co = 0;
    uint32_t po = 2u * STG_MK;
    for (int t = 0; t < ntiles; t++) {
        CP_WAIT1();
        __syncthreads();

        if (t + 2 < ntiles) {
            const int k0 = (t + 2) * BK;
            const __half* ap = Ab + (size_t)l_row * QQ + k0 + l_c8;
            const __half* bp = Bb + (size_t)l_row * QQ + k0 + l_c8;
#pragma unroll
            for (int u = 0; u < 4; u++) {
                cp_async16(asBase + po + wOff[u], ap + (size_t)(32 * u) * QQ);
                cp_async16(bsBase + po + wOff[u], bp + (size_t)(32 * u) * QQ);
            }
            CP_COMMIT();
        }
        ROT3(po, (uint32_t)STG_MK);

#pragma unroll
        for (int ks = 0; ks < 4; ks++)
            mma_step_mk(acc, asBase + co, bsBase + co, offs, ks);
        ROT3(co, (uint32_t)STG_MK);
    }

    __half* Cb = g_ph + (size_t)b * SS * QQ;
#pragma unroll
    for (int i = 0; i < 2; i++) {
        const int row0 = m0 + warp_row * 32 + i * 16 + (lane >> 2);
#pragma unroll
        for (int j = 0; j < 8; j++) {
            const int col = n0 + warp_col * 64 + j * 8 + 2 * (lane & 3);
#pragma unroll
            for (int r = 0; r < 2; r++) {
                const size_t off = (size_t)(row0 + r * 8) * QQ + col;
                __half2 h = __floats2half2_rn(acc[i][j][r * 2 + 0],
                                              acc[i][j][r * 2 + 1]);
                *reinterpret_cast<__half2*>(Cb + off) = h;
            }
        }
    }
}

// ============================================================================
// Kernel C: out[b][q][d] = sum_s ph[b][s][q] * srch[b][s][d]  (KM layout, K=s)
// ldmatrix.trans both operands. BK=64, 3-stage.
// ============================================================================
__global__ void __launch_bounds__(256, 2)
gemm_out(float* __restrict__ C)
{
    extern __shared__ uint32_t smem[];
    const uint32_t sBase = (uint32_t)__cvta_generic_to_shared(smem);
    const uint32_t asBase = sBase;
    const uint32_t bsBase = sBase + 3 * STG_KM;

    const int tid = threadIdx.x;
    const int wid = tid >> 5;
    const int lane = tid & 31;
    const int warp_row = wid >> 1;
    const int warp_col = wid & 1;

    const int b  = blockIdx.z;
    const int m0 = blockIdx.y * BM;   // q
    const int n0 = blockIdx.x * BN;   // d

    const __half* Ab = g_ph + (size_t)b * SS * QQ + m0;
    const __half* Bb = g_srch + (size_t)b * SS * DD + n0;

    const int lk = tid >> 3;          // 0..31
    const int lc = (tid & 7) * 8;     // halves 0..56

    uint32_t w[4];
    int wr[4], wc[4];
#pragma unroll
    for (int u = 0; u < 4; u++) {
        wr[u] = lk + 32 * (u >> 1);
        wc[u] = lc + 64 * (u & 1);
        w[u] = (uint32_t)((wr[u] * LDMH + wc[u]) * 2);
    }

    const int sel = lane >> 3, rin = lane & 7;
    uint32_t oa[2], ob[4];
#pragma unroll
    for (int i = 0; i < 2; i++)
        oa[i] = (uint32_t)((((sel >> 1) * 8 + rin) * LDMH
                           + warp_row * 32 + i * 16 + (sel & 1) * 8) * 2);
#pragma unroll
    for (int jp = 0; jp < 4; jp++)
        ob[jp] = (uint32_t)((((sel & 1) * 8 + rin) * LDMH
                           + warp_col * 64 + jp * 16 + (sel >> 1) * 8) * 2);

    float acc[2][8][4];
#pragma unroll
    for (int i = 0; i < 2; i++)
#pragma unroll
        for (int j = 0; j < 8; j++)
#pragma unroll
            for (int r = 0; r < 4; r++) acc[i][j][r] = 0.f;

    const int ntiles = SS / BK;   // 32

#pragma unroll
    for (int p = 0; p < 2; p++) {
        const int k0 = p * BK;
        const uint32_t so = (uint32_t)p * STG_KM;
#pragma unroll
        for (int u = 0; u < 4; u++) {
            cp_async16(asBase + so + w[u], Ab + (size_t)(k0 + wr[u]) * QQ + wc[u]);
            cp_async16(bsBase + so + w[u], Bb + (size_t)(k0 + wr[u]) * DD + wc[u]);
        }
        CP_COMMIT();
    }

    uint32_t co = 0;
    uint32_t po = 2u * STG_KM;
    for (int t = 0; t < ntiles; t++) {
        CP_WAIT1();
        __syncthreads();

        if (t + 2 < ntiles) {
            const int k0 = (t + 2) * BK;
#pragma unroll
            for (int u = 0; u < 4; u++) {
                cp_async16(asBase + po + w[u], Ab + (size_t)(k0 + wr[u]) * QQ + wc[u]);
                cp_async16(bsBase + po + w[u], Bb + (size_t)(k0 + wr[u]) * DD + wc[u]);
            }
            CP_COMMIT();
        }
        ROT3(po, (uint32_t)STG_KM);

        const uint32_t aB = asBase + co;
        const uint32_t bB = bsBase + co;

#pragma unroll
        for (int ks = 0; ks < 4; ks++) {
            const uint32_t kadd = (uint32_t)(ks * 16 * LDMH * 2);
            uint32_t afr[2][4];
            ldsm_x4_t(afr[0], aB + oa[0] + kadd);
            ldsm_x4_t(afr[1], aB + oa[1] + kadd);
            uint32_t bfr[4][4];
#pragma unroll
            for (int jp = 0; jp < 4; jp++)
                ldsm_x4_t(bfr[jp], bB + ob[jp] + kadd);
#pragma unroll
            for (int i = 0; i < 2; i++)
#pragma unroll
                for (int j = 0; j < 8; j++)
                    mma_f16(acc[i][j], afr[i], &bfr[j >> 1][(j & 1) * 2]);
        }
        ROT3(co, (uint32_t)STG_KM);
    }

    float* Cb = C + (size_t)b * QQ * DD;
#pragma unroll
    for (int i = 0; i < 2; i++) {
        const int row0 = m0 + warp_row * 32 + i * 16 + (lane >> 2);
#pragma unroll
        for (int j = 0; j < 8; j++) {
            const int col = n0 + warp_col * 64 + j * 8 + 2 * (lane & 3);
#pragma unroll
            for (int r = 0; r < 2; r++) {
                const size_t off = (size_t)(row0 + r * 8) * DD + col;
                float2 v;
                v.x = acc[i][j][r * 2 + 0];
                v.y = acc[i][j][r * 2 + 1];
                *reinterpret_cast<float2*>(Cb + off) = v;
            }
        }
    }
}

// ---------------------------------------------------------------------------
// Merged elementwise f32 -> fp16 over three buffers (1 float4/thread)
// ---------------------------------------------------------------------------
#define CVT_N0 ((BB * SS * DD) / 4)   // src
#define CVT_N1 ((BB * QQ * DD) / 4)   // qry
#define CVT_N2 ((SS * DD) / 4)        // wq
#define CVT_TOTAL (CVT_N0 + CVT_N1 + CVT_N2)

__global__ void k_cvt_all(const float4* __restrict__ src, uint2* __restrict__ srch,
                          const float4* __restrict__ qry, uint2* __restrict__ qryh,
                          const float4* __restrict__ wq,  uint2* __restrict__ wqh)
{
    int i = blockIdx.x * blockDim.x + threadIdx.x;
    if (i >= CVT_TOTAL) return;
    const float4* in;
    uint2* out;
    int idx;
    if (i < CVT_N0)                { in = src; out = srch; idx = i; }
    else if (i < CVT_N0 + CVT_N1)  { in = qry; out = qryh; idx = i - CVT_N0; }
    else                           { in = wq;  out = wqh;  idx = i - CVT_N0 - CVT_N1; }
    float4 v = in[idx];
    uint2 o;
    o.x = h2_as_u32(__floats2half2_rn(v.x, v.y));
    o.y = h2_as_u32(__floats2half2_rn(v.z, v.w));
    out[idx] = o;
}

// ---------------------------------------------------------------------------
// Merged tiled transpose f32 -> fp16 for wk (D x Q) and kern (Q x Q).
// ---------------------------------------------------------------------------
__global__ void k_transpose2(const float* __restrict__ wk, __half* __restrict__ wkT,
                             const float* __restrict__ kern, __half* __restrict__ kernT)
{
    __shared__ float tile[32][33];
    const float* in;
    __half* out;
    int R, C, r0;
    if (blockIdx.y < DD / 32) {
        in = wk; out = wkT; R = DD; C = QQ; r0 = blockIdx.y * 32;
    } else {
        in = kern; out = kernT; R = QQ; C = QQ; r0 = (blockIdx.y - DD / 32) * 32;
    }
    const int c0 = blockIdx.x * 32;

#pragma unroll
    for (int i = threadIdx.y; i < 32; i += 8)
        tile[i][threadIdx.x] = in[(size_t)(r0 + i) * C + c0 + threadIdx.x];
    __syncthreads();
#pragma unroll
    for (int i = threadIdx.y; i < 32; i += 8)
        out[(size_t)(c0 + i) * R + r0 + threadIdx.x] = __float2half_rn(tile[threadIdx.x][i]);
}

// ---------------------------------------------------------------------------
// In-place fp16 row softmax on g_ph: read fp16 logits, write fp16 probs.
// f32 math in SMEM; one 4KB read + 4KB write per row.
// ---------------------------------------------------------------------------
__global__ void __launch_bounds__(256)
k_softmax()
{
    __shared__ float rowv[QQ];   // 8 KB
    __shared__ float red[32];

    __half2* p = reinterpret_cast<__half2*>(g_ph + (size_t)blockIdx.x * QQ);
    const int tid = threadIdx.x;  // 256

    // load fp16 -> f32 smem, compute max
    float m = -INFINITY;
#pragma unroll
    for (int i = tid; i < QQ / 2; i += 256) {
        float2 f = __half22float2(p[i]);
        rowv[2 * i + 0] = f.x;
        rowv[2 * i + 1] = f.y;
        m = fmaxf(m, fmaxf(f.x, f.y));
    }
#pragma unroll
    for (int o = 16; o > 0; o >>= 1) m = fmaxf(m, __shfl_xor_sync(0xffffffffu, m, o));
    if ((tid & 31) == 0) red[tid >> 5] = m;
    __syncthreads();
    if (tid < 32) {
        float v = (tid < 8) ? red[tid] : -INFINITY;
#pragma unroll
        for (int o = 4; o > 0; o >>= 1) v = fmaxf(v, __shfl_xor_sync(0xffffffffu, v, o));
        red[tid] = v;
    }
    __syncthreads();
    m = red[0];
    __syncthreads();

    // exp + sum (in smem)
    float sum = 0.f;
#pragma unroll
    for (int i = tid; i < QQ; i += 256) {
        float e = __expf(rowv[i] - m);
        rowv[i] = e;
        sum += e;
    }
#pragma unroll
    for (int o = 16; o > 0; o >>= 1) sum += __shfl_xor_sync(0xffffffffu, sum, o);
    if ((tid & 31) == 0) red[tid >> 5] = sum;
    __syncthreads();
    if (tid < 32) {
        float v = (tid < 8) ? red[tid] : 0.f;
#pragma unroll
        for (int o = 4; o > 0; o >>= 1) v += __shfl_xor_sync(0xffffffffu, v, o);
        red[tid] = v;
    }
    __syncthreads();
    const float inv = 1.0f / red[0];

    // normalize + fp16 store (in place)
#pragma unroll
    for (int i = tid; i < QQ / 2; i += 256)
        p[i] = __floats2half2_rn(rowv[2 * i + 0] * inv, rowv[2 * i + 1] * inv);
}

// ---------------------------------------------------------------------------
// Launcher
// ---------------------------------------------------------------------------
extern "C" void kernel_launch(void* const* d_in, const int* in_sizes, int n_in,
                              void* d_out, int out_size)
{
    const float* src  = (const float*)d_in[0];  // (B,S,D)
    const float* qry  = (const float*)d_in[1];  // (B,Q,D)
    const float* kern = (const float*)d_in[2];  // (Q,T)
    const float* wk   = (const float*)d_in[3];  // (D,Q)
    const float* wq   = (const float*)d_in[4];  // (S,D)
    float* out = (float*)d_out;                 // (B,Q,D)

    __half *srch, *qryh, *wqh, *wkTh, *kernTh;
    cudaGetSymbolAddress((void**)&srch, g_srch);
    cudaGetSymbolAddress((void**)&qryh, g_qryh);
    cudaGetSymbolAddress((void**)&wqh, g_wqh);
    cudaGetSymbolAddress((void**)&wkTh, g_wkTh);
    cudaGetSymbolAddress((void**)&kernTh, g_kernTh);

    cudaFuncSetAttribute(gemm_fatt, cudaFuncAttributeMaxDynamicSharedMemorySize, GSMEM_MK);
    cudaFuncSetAttribute(gemm_sim,  cudaFuncAttributeMaxDynamicSharedMemorySize, GSMEM_MK);
    cudaFuncSetAttribute(gemm_out,  cudaFuncAttributeMaxDynamicSharedMemorySize, GSMEM_KM);

    // 0) operand prep: merged fp16 conversion + merged weight transposes
    k_cvt_all<<<(CVT_TOTAL + 255) / 256, 256>>>(
        (const float4*)src, (uint2*)srch,
        (const float4*)qry, (uint2*)qryh,
        (const float4*)wq,  (uint2*)wqh);
    k_transpose2<<<dim3(QQ / 32, DD / 32 + QQ / 32), dim3(32, 8)>>>(wk, wkTh, kern, kernTh);

    // 1) merged f_att: t1h = tanh(src@wk + wq@qry^T)
    gemm_fatt<<<dim3(QQ / BN, SS / BM, BB), 256, GSMEM_MK>>>();

    // 2) sim logits (fp16) -> g_ph
    gemm_sim<<<dim3(QQ / BN, SS / BM, BB), 256, GSMEM_MK>>>();

    // 3) in-place fp16 softmax on g_ph
    k_softmax<<<BB * SS, 256>>>();

    // 4) out = probs^T @ src
    gemm_out<<<dim3(DD / BN, QQ / BM, BB), 256, GSMEM_KM>>>(out);
}